// round 1
// baseline (speedup 1.0000x reference)
#include <cuda_runtime.h>
#include <cstdint>
#include <cstddef>

#define R_ANCH 120000
#define B_BATCH 4
#define G_GT 64
#define C_CLS 80
#define NTILES ((R_ANCH + 255) / 256)   // 469

// scratch (no allocations allowed)
__device__ unsigned d_mpg[B_BATCH * G_GT];   // max IoU per (b, gt), as float bits
__device__ double   d_cls_sum;
__device__ double   d_box_sum;
__device__ int      d_fg_cnt;

// Bit-exact IoU: every op is an explicit correctly-rounded intrinsic so that
// kernel A and kernel B produce IDENTICAL bits (required for the lq equality
// test) and match XLA's fp32 lowering at the 0.5/0.4 thresholds.
__device__ __forceinline__ float iou_exact(const float4 a, const float4 g, float area_g) {
    float area_a = __fmul_rn(__fsub_rn(a.z, a.x), __fsub_rn(a.w, a.y));
    float ltx = fmaxf(a.x, g.x);
    float lty = fmaxf(a.y, g.y);
    float rbx = fminf(a.z, g.z);
    float rby = fminf(a.w, g.w);
    float wx = fmaxf(__fsub_rn(rbx, ltx), 0.0f);
    float wy = fmaxf(__fsub_rn(rby, lty), 0.0f);
    float inter = __fmul_rn(wx, wy);
    float uni = __fsub_rn(__fadd_rn(area_a, area_g), inter);
    return __fdiv_rn(inter, uni);
}

__global__ void k_init() {
    int t = threadIdx.x;
    if (t < B_BATCH * G_GT) d_mpg[t] = 0u;
    if (t == 0) { d_cls_sum = 0.0; d_box_sum = 0.0; d_fg_cnt = 0; }
}

// Kernel A: max IoU over all anchors, per (batch, gt).
// Block = 256 threads: thread owns gt g = tid&63, scans anchor sub-slice tid>>6.
// Anchors tiled through shared memory (broadcast reads), so anchors cross L2
// only ~once per batch instead of 64x.
__global__ void __launch_bounds__(256) k_maxpergt(
        const float4* __restrict__ anchors,
        const float4* __restrict__ gt_boxes) {
    const int b   = blockIdx.y;
    const int g   = threadIdx.x & 63;
    const int sub = threadIdx.x >> 6;

    __shared__ float4   sA[256];
    __shared__ unsigned smax[64];
    if (threadIdx.x < 64) smax[threadIdx.x] = 0u;

    float4 gb = gt_boxes[b * G_GT + g];
    float area_g = __fmul_rn(__fsub_rn(gb.z, gb.x), __fsub_rn(gb.w, gb.y));
    float m = 0.0f;

    for (int tile = blockIdx.x; tile < NTILES; tile += gridDim.x) {
        int r = tile * 256 + threadIdx.x;
        // padded anchor (0,0,0,0) yields IoU 0 -> harmless for the max
        sA[threadIdx.x] = (r < R_ANCH) ? anchors[r] : make_float4(0.f, 0.f, 0.f, 0.f);
        __syncthreads();
        #pragma unroll 8
        for (int j = sub; j < 256; j += 4) {
            float iou = iou_exact(sA[j], gb, area_g);
            m = fmaxf(m, iou);
        }
        __syncthreads();
    }
    atomicMax(&smax[g], __float_as_uint(m));   // IoU >= 0 -> uint order == float order
    __syncthreads();
    if (threadIdx.x < 64)
        atomicMax(&d_mpg[b * G_GT + threadIdx.x], smax[threadIdx.x]);
}

__device__ __forceinline__ float focal_elem(float x, bool t1) {
    float e  = __expf(-fabsf(x));                 // EX2
    float L  = __logf(1.0f + e);                  // LG2  (= stable log1p term)
    float rr = __fdividef(1.0f, 1.0f + e);        // RCP
    float p  = (x >= 0.0f) ? rr : e * rr;         // sigmoid(x)
    if (t1) {
        float q = 1.0f - p;
        return 0.25f * q * q * (fmaxf(-x, 0.0f) + L);   // alpha * (1-p)^2 * ce(t=1)
    } else {
        return 0.75f * p * p * (fmaxf(x, 0.0f) + L);    // (1-alpha) * p^2 * ce(t=0)
    }
}

// Kernel B: per-anchor matching (recompute IoU row), focal + smooth-L1, and
// hierarchical reduction (warp shuffle -> shared -> one double atomic per block).
__global__ void __launch_bounds__(256) k_loss(
        const float*  __restrict__ logits,
        const float4* __restrict__ deltas,
        const float4* __restrict__ anchors,
        const float4* __restrict__ gt_boxes,
        const int*    __restrict__ gt_labels) {
    const int b = blockIdx.y;
    const int r = blockIdx.x * 256 + threadIdx.x;

    __shared__ float4 sG[64];
    __shared__ float  sGA[64];
    __shared__ float  sM[64];
    __shared__ int    sL[64];
    if (threadIdx.x < 64) {
        float4 gb = gt_boxes[b * G_GT + threadIdx.x];
        sG[threadIdx.x]  = gb;
        sGA[threadIdx.x] = __fmul_rn(__fsub_rn(gb.z, gb.x), __fsub_rn(gb.w, gb.y));
        sM[threadIdx.x]  = __uint_as_float(d_mpg[b * G_GT + threadIdx.x]);
        sL[threadIdx.x]  = gt_labels[b * G_GT + threadIdx.x];
    }
    __syncthreads();

    float cls = 0.0f, box = 0.0f;
    int fg = 0;
    if (r < R_ANCH) {
        float4 a = anchors[r];
        float best = -1.0f;
        int   bi = 0;
        int   lq = 0;
        #pragma unroll 4
        for (int gi = 0; gi < G_GT; gi++) {
            float iou = iou_exact(a, sG[gi], sGA[gi]);
            if (iou > best) { best = iou; bi = gi; }   // first-index tie-break
            float mp = sM[gi];
            lq |= (iou == mp) && (mp > 0.0f);
        }
        fg = (best >= 0.5f) || lq;
        int valid = fg || (best < 0.4f);

        if (valid) {
            int mc = fg ? sL[bi] : -1;
            const float4* lp = (const float4*)(logits + ((size_t)b * R_ANCH + r) * C_CLS);
            #pragma unroll 4
            for (int c4 = 0; c4 < C_CLS / 4; c4++) {
                float4 v = lp[c4];
                int c = c4 * 4;
                cls += focal_elem(v.x, c + 0 == mc);
                cls += focal_elem(v.y, c + 1 == mc);
                cls += focal_elem(v.z, c + 2 == mc);
                cls += focal_elem(v.w, c + 3 == mc);
            }
        }
        if (fg) {
            float4 gb = sG[bi];
            float sw  = a.z - a.x,  sh  = a.w - a.y;
            float scx = a.x + 0.5f * sw, scy = a.y + 0.5f * sh;
            float tw  = gb.z - gb.x, th  = gb.w - gb.y;
            float tcx = gb.x + 0.5f * tw, tcy = gb.y + 0.5f * th;
            float gd0 = (tcx - scx) / sw;
            float gd1 = (tcy - scy) / sh;
            float gd2 = logf(tw / sw);
            float gd3 = logf(th / sh);
            float4 pd = deltas[(size_t)b * R_ANCH + r];
            float d0 = pd.x - gd0, d1 = pd.y - gd1, d2 = pd.z - gd2, d3 = pd.w - gd3;
            float a0 = fabsf(d0), a1 = fabsf(d1), a2 = fabsf(d2), a3 = fabsf(d3);
            // smooth L1, beta = 0.1:  a<beta ? 0.5*d*d/beta : a - 0.5*beta
            box += (a0 < 0.1f) ? 5.0f * d0 * d0 : a0 - 0.05f;
            box += (a1 < 0.1f) ? 5.0f * d1 * d1 : a1 - 0.05f;
            box += (a2 < 0.1f) ? 5.0f * d2 * d2 : a2 - 0.05f;
            box += (a3 < 0.1f) ? 5.0f * d3 * d3 : a3 - 0.05f;
        }
    }

    // reduction: warp shuffle -> shared -> one atomic set per block
    const unsigned mask = 0xffffffffu;
    #pragma unroll
    for (int off = 16; off; off >>= 1) {
        cls += __shfl_xor_sync(mask, cls, off);
        box += __shfl_xor_sync(mask, box, off);
    }
    int wfg = __popc(__ballot_sync(mask, fg));

    __shared__ float rc[8], rb[8];
    __shared__ int   rf[8];
    int wid = threadIdx.x >> 5, lane = threadIdx.x & 31;
    if (lane == 0) { rc[wid] = cls; rb[wid] = box; rf[wid] = wfg; }
    __syncthreads();
    if (threadIdx.x == 0) {
        float tc = 0.f, tb = 0.f; int tf = 0;
        #pragma unroll
        for (int i = 0; i < 8; i++) { tc += rc[i]; tb += rb[i]; tf += rf[i]; }
        atomicAdd(&d_cls_sum, (double)tc);
        atomicAdd(&d_box_sum, (double)tb);
        atomicAdd(&d_fg_cnt, tf);
    }
}

__global__ void k_final(float* out) {
    float norm = fmaxf(1.0f, (float)d_fg_cnt);
    out[0] = (float)(d_cls_sum / (double)norm);
    out[1] = (float)(d_box_sum / (double)norm);
}

extern "C" void kernel_launch(void* const* d_in, const int* in_sizes, int n_in,
                              void* d_out, int out_size) {
    // Identify inputs by element count (all distinct for this problem).
    const float* logits  = nullptr;
    const float* deltas  = nullptr;
    const float* anchors = nullptr;
    const float* gtb     = nullptr;
    const int*   gtl     = nullptr;
    for (int i = 0; i < n_in; i++) {
        switch (in_sizes[i]) {
            case 38400000: logits  = (const float*)d_in[i]; break;  // [4,120000,80]
            case 1920000:  deltas  = (const float*)d_in[i]; break;  // [4,120000,4]
            case 480000:   anchors = (const float*)d_in[i]; break;  // [120000,4]
            case 1024:     gtb     = (const float*)d_in[i]; break;  // [4,64,4]
            case 256:      gtl     = (const int*)d_in[i];   break;  // [4,64]
            default: break;
        }
    }

    k_init<<<1, 256>>>();
    {
        dim3 grid(148, B_BATCH);
        k_maxpergt<<<grid, 256>>>((const float4*)anchors, (const float4*)gtb);
    }
    {
        dim3 grid((R_ANCH + 255) / 256, B_BATCH);
        k_loss<<<grid, 256>>>(logits, (const float4*)deltas,
                              (const float4*)anchors, (const float4*)gtb, gtl);
    }
    k_final<<<1, 1>>>((float*)d_out);
}

// round 9
// speedup vs baseline: 3.5309x; 3.5309x over previous
#include <cuda_runtime.h>
#include <cstdint>
#include <cstddef>

#define R_ANCH 120000
#define B_BATCH 4
#define G_GT 64
#define C_CLS 80
#define NTILES ((R_ANCH + 255) / 256)   // 469

// scratch (no allocations allowed; static zero-init covers the first call,
// k_final resets after each use so every graph replay sees the same state)
__device__ unsigned d_mpg[B_BATCH * G_GT];   // max IoU per (b, gt), as float bits
__device__ double   d_cls_sum;
__device__ double   d_box_sum;
__device__ int      d_fg_cnt;

// IoU with fast division. The lq equality test only requires kernel A and
// kernel B to produce mutually bit-identical values -> same intrinsic
// sequence in both (explicit rn intrinsics prevent contraction variance,
// __fdividef expands deterministically to RCP+MUL). Error vs the reference's
// correctly-rounded div is <=2ulp, negligible at the 0.5/0.4 thresholds.
__device__ __forceinline__ float iou_fast(const float4 a, const float4 g, float area_g) {
    float area_a = __fmul_rn(__fsub_rn(a.z, a.x), __fsub_rn(a.w, a.y));
    float wx = fmaxf(__fsub_rn(fminf(a.z, g.z), fmaxf(a.x, g.x)), 0.0f);
    float wy = fmaxf(__fsub_rn(fminf(a.w, g.w), fmaxf(a.y, g.y)), 0.0f);
    float inter = __fmul_rn(wx, wy);
    float uni = __fsub_rn(__fadd_rn(area_a, area_g), inter);
    return __fdividef(inter, uni);
}

// Kernel A: max IoU over all anchors, per (batch, gt).
// Thread owns gt g = tid&63, scans anchor sub-slice tid>>6; anchors tiled
// through shared memory with broadcast reads.
__global__ void __launch_bounds__(256) k_maxpergt(
        const float4* __restrict__ anchors,
        const float4* __restrict__ gt_boxes) {
    const int b   = blockIdx.y;
    const int g   = threadIdx.x & 63;
    const int sub = threadIdx.x >> 6;

    __shared__ float4   sA[256];
    __shared__ unsigned smax[64];
    if (threadIdx.x < 64) smax[threadIdx.x] = 0u;

    float4 gb = gt_boxes[b * G_GT + g];
    float area_g = __fmul_rn(__fsub_rn(gb.z, gb.x), __fsub_rn(gb.w, gb.y));
    float m = 0.0f;

    for (int tile = blockIdx.x; tile < NTILES; tile += gridDim.x) {
        int r = tile * 256 + threadIdx.x;
        sA[threadIdx.x] = (r < R_ANCH) ? anchors[r] : make_float4(0.f, 0.f, 0.f, 0.f);
        __syncthreads();
        #pragma unroll 8
        for (int j = sub; j < 256; j += 4) {
            float iou = iou_fast(sA[j], gb, area_g);
            m = fmaxf(m, iou);
        }
        __syncthreads();
    }
    atomicMax(&smax[g], __float_as_uint(m));   // IoU >= 0 -> uint order == float order
    __syncthreads();
    if (threadIdx.x < 64)
        atomicMax(&d_mpg[b * G_GT + threadIdx.x], smax[threadIdx.x]);
}

// focal term for t=0: (1-alpha) * sigmoid(x)^2 * softplus(x)
__device__ __forceinline__ float term0(float x) {
    float e  = __expf(-fabsf(x));
    float sp = fmaxf(x, 0.0f) + __logf(1.0f + e);      // softplus(x)
    float rr = __fdividef(1.0f, 1.0f + e);
    float p  = (x >= 0.0f) ? rr : e * rr;              // sigmoid(x)
    return 0.75f * p * p * sp;
}
// focal term for t=1: alpha * (1-sigmoid(x))^2 * softplus(-x)
__device__ __forceinline__ float term1(float x) {
    float e   = __expf(-fabsf(x));
    float spn = fmaxf(-x, 0.0f) + __logf(1.0f + e);    // softplus(-x)
    float rr  = __fdividef(1.0f, 1.0f + e);
    float p   = (x >= 0.0f) ? rr : e * rr;
    float q   = 1.0f - p;
    return 0.25f * q * q * spn;
}

// Kernel B: per-anchor matching (recompute IoU row), focal + smooth-L1,
// hierarchical reduction -> one double atomic set per block.
__global__ void __launch_bounds__(256) k_loss(
        const float*  __restrict__ logits,
        const float4* __restrict__ deltas,
        const float4* __restrict__ anchors,
        const float4* __restrict__ gt_boxes,
        const int*    __restrict__ gt_labels) {
    const int b = blockIdx.y;
    const int r = blockIdx.x * 256 + threadIdx.x;

    __shared__ float4 sG[64];
    __shared__ float  sGA[64];
    __shared__ float  sM[64];
    __shared__ int    sL[64];
    if (threadIdx.x < 64) {
        float4 gb = gt_boxes[b * G_GT + threadIdx.x];
        sG[threadIdx.x]  = gb;
        sGA[threadIdx.x] = __fmul_rn(__fsub_rn(gb.z, gb.x), __fsub_rn(gb.w, gb.y));
        sM[threadIdx.x]  = __uint_as_float(d_mpg[b * G_GT + threadIdx.x]);
        sL[threadIdx.x]  = gt_labels[b * G_GT + threadIdx.x];
    }
    __syncthreads();

    float cls = 0.0f, box = 0.0f;
    int fg = 0;
    if (r < R_ANCH) {
        float4 a = anchors[r];
        float best = -1.0f;
        int   bi = 0;
        int   lq = 0;
        #pragma unroll 8
        for (int gi = 0; gi < G_GT; gi++) {
            float iou = iou_fast(a, sG[gi], sGA[gi]);
            if (iou > best) { best = iou; bi = gi; }   // first-index tie-break
            float mp = sM[gi];
            lq |= (iou == mp) && (mp > 0.0f);
        }
        fg = (best >= 0.5f) || lq;
        int valid = fg || (best < 0.4f);

        if (valid) {
            const float4* lp = (const float4*)(logits + ((size_t)b * R_ANCH + r) * C_CLS);
            #pragma unroll 4
            for (int c4 = 0; c4 < C_CLS / 4; c4++) {
                float4 v = lp[c4];
                cls += term0(v.x) + term0(v.y) + term0(v.z) + term0(v.w);
            }
        }
        if (fg) {
            // swap the matched class's t=0 term for its t=1 term
            float xm = logits[((size_t)b * R_ANCH + r) * C_CLS + sL[bi]];
            cls += term1(xm) - term0(xm);

            float4 gb = sG[bi];
            float sw  = a.z - a.x,  sh  = a.w - a.y;
            float scx = a.x + 0.5f * sw, scy = a.y + 0.5f * sh;
            float tw  = gb.z - gb.x, th  = gb.w - gb.y;
            float tcx = gb.x + 0.5f * tw, tcy = gb.y + 0.5f * th;
            float gd0 = __fdividef(tcx - scx, sw);
            float gd1 = __fdividef(tcy - scy, sh);
            float gd2 = __logf(__fdividef(tw, sw));
            float gd3 = __logf(__fdividef(th, sh));
            float4 pd = deltas[(size_t)b * R_ANCH + r];
            float d0 = pd.x - gd0, d1 = pd.y - gd1, d2 = pd.z - gd2, d3 = pd.w - gd3;
            float a0 = fabsf(d0), a1 = fabsf(d1), a2 = fabsf(d2), a3 = fabsf(d3);
            // smooth L1, beta = 0.1
            box += (a0 < 0.1f) ? 5.0f * d0 * d0 : a0 - 0.05f;
            box += (a1 < 0.1f) ? 5.0f * d1 * d1 : a1 - 0.05f;
            box += (a2 < 0.1f) ? 5.0f * d2 * d2 : a2 - 0.05f;
            box += (a3 < 0.1f) ? 5.0f * d3 * d3 : a3 - 0.05f;
        }
    }

    // reduction: warp shuffle -> shared -> one atomic set per block
    const unsigned mask = 0xffffffffu;
    #pragma unroll
    for (int off = 16; off; off >>= 1) {
        cls += __shfl_xor_sync(mask, cls, off);
        box += __shfl_xor_sync(mask, box, off);
    }
    int wfg = __popc(__ballot_sync(mask, fg));

    __shared__ float rc[8], rb[8];
    __shared__ int   rf[8];
    int wid = threadIdx.x >> 5, lane = threadIdx.x & 31;
    if (lane == 0) { rc[wid] = cls; rb[wid] = box; rf[wid] = wfg; }
    __syncthreads();
    if (threadIdx.x == 0) {
        float tc = 0.f, tb = 0.f; int tf = 0;
        #pragma unroll
        for (int i = 0; i < 8; i++) { tc += rc[i]; tb += rb[i]; tf += rf[i]; }
        atomicAdd(&d_cls_sum, (double)tc);
        atomicAdd(&d_box_sum, (double)tb);
        atomicAdd(&d_fg_cnt, tf);
    }
}

// finalize AND reset scratch for the next replay (replay-idempotent)
__global__ void k_final(float* out) {
    int t = threadIdx.x;
    if (t == 0) {
        float norm = fmaxf(1.0f, (float)d_fg_cnt);
        out[0] = (float)(d_cls_sum / (double)norm);
        out[1] = (float)(d_box_sum / (double)norm);
        d_cls_sum = 0.0; d_box_sum = 0.0; d_fg_cnt = 0;
    }
    if (t < B_BATCH * G_GT) d_mpg[t] = 0u;
}

extern "C" void kernel_launch(void* const* d_in, const int* in_sizes, int n_in,
                              void* d_out, int out_size) {
    const float* logits  = nullptr;
    const float* deltas  = nullptr;
    const float* anchors = nullptr;
    const float* gtb     = nullptr;
    const int*   gtl     = nullptr;
    for (int i = 0; i < n_in; i++) {
        switch (in_sizes[i]) {
            case 38400000: logits  = (const float*)d_in[i]; break;  // [4,120000,80]
            case 1920000:  deltas  = (const float*)d_in[i]; break;  // [4,120000,4]
            case 480000:   anchors = (const float*)d_in[i]; break;  // [120000,4]
            case 1024:     gtb     = (const float*)d_in[i]; break;  // [4,64,4]
            case 256:      gtl     = (const int*)d_in[i];   break;  // [4,64]
            default: break;
        }
    }

    {
        dim3 grid(148, B_BATCH);
        k_maxpergt<<<grid, 256>>>((const float4*)anchors, (const float4*)gtb);
    }
    {
        dim3 grid((R_ANCH + 255) / 256, B_BATCH);
        k_loss<<<grid, 256>>>(logits, (const float4*)deltas,
                              (const float4*)anchors, (const float4*)gtb, gtl);
    }
    k_final<<<1, 256>>>((float*)d_out);
}

// round 10
// speedup vs baseline: 3.6329x; 1.0289x over previous
#include <cuda_runtime.h>
#include <cstdint>
#include <cstddef>

#define R_ANCH 120000
#define B_BATCH 4
#define G_GT 64
#define C_CLS 80
#define NTILES ((R_ANCH + 255) / 256)   // 469

// scratch (no allocations; static zero-init covers first call, k_final resets)
__device__ unsigned d_mpg[B_BATCH * G_GT];
__device__ double   d_cls_sum;
__device__ double   d_box_sum;
__device__ int      d_fg_cnt;

// IoU core with precomputed anchor area. Same intrinsic sequence in kernel A
// and kernel B -> bit-identical values, required for the lq equality test.
__device__ __forceinline__ float iou_core(const float4 a, float area_a,
                                          const float4 g, float area_g) {
    float wx = fmaxf(__fsub_rn(fminf(a.z, g.z), fmaxf(a.x, g.x)), 0.0f);
    float wy = fmaxf(__fsub_rn(fminf(a.w, g.w), fmaxf(a.y, g.y)), 0.0f);
    float inter = __fmul_rn(wx, wy);
    float uni = __fsub_rn(__fadd_rn(area_a, area_g), inter);
    return __fdividef(inter, uni);
}
__device__ __forceinline__ float box_area(const float4 v) {
    return __fmul_rn(__fsub_rn(v.z, v.x), __fsub_rn(v.w, v.y));
}

// Kernel A: max IoU per (batch, gt). One 256-anchor tile per block (perfect
// balance, 8 CTAs/SM -> full occupancy). Thread owns gt g = tid&63 and scans
// the tile sub-slice tid>>6; anchors + precomputed areas in shared (broadcast).
__global__ void __launch_bounds__(256) k_maxpergt(
        const float4* __restrict__ anchors,
        const float4* __restrict__ gt_boxes) {
    const int b    = blockIdx.y;
    const int tile = blockIdx.x;
    const int g    = threadIdx.x & 63;
    const int sub  = threadIdx.x >> 6;

    __shared__ float4   sA[256];
    __shared__ float    sAr[256];
    __shared__ unsigned smax[64];
    if (threadIdx.x < 64) smax[threadIdx.x] = 0u;

    int r = tile * 256 + threadIdx.x;
    float4 av = (r < R_ANCH) ? anchors[r] : make_float4(0.f, 0.f, 0.f, 0.f);
    sA[threadIdx.x]  = av;
    sAr[threadIdx.x] = box_area(av);   // padded anchor -> area 0 -> iou 0

    float4 gb = gt_boxes[b * G_GT + g];
    float area_g = box_area(gb);
    __syncthreads();

    float m = 0.0f;
    #pragma unroll 8
    for (int j = sub; j < 256; j += 4) {
        float iou = iou_core(sA[j], sAr[j], gb, area_g);
        m = fmaxf(m, iou);
    }
    atomicMax(&smax[g], __float_as_uint(m));   // iou >= 0: uint order == float order
    __syncthreads();
    if (threadIdx.x < 64)
        atomicMax(&d_mpg[b * G_GT + threadIdx.x], smax[threadIdx.x]);
}

// exact t=0 focal term: (1-alpha)*sigmoid(x)^2*softplus(x)  (fallback path)
__device__ __forceinline__ float term0_exact(float x) {
    float e  = __expf(-fabsf(x));
    float sp = fmaxf(x, 0.0f) + __logf(1.0f + e);
    float rr = __fdividef(1.0f, 1.0f + e);
    float p  = (x >= 0.0f) ? rr : e * rr;
    return 0.75f * p * p * sp;
}
// fast t=0 focal: for e=exp(x) < 1/16,
//   term0 = 0.75*e^3*(1 - 5/2 e + 13/3 e^2 - 77/12 e^3)
// (product of series for ln(1+e)/e and (1+e)^-2; rel err <=1.3e-4 at the
// guard boundary, ~1e-7 at this problem's logit range e in [0.005,0.02]).
__device__ __forceinline__ float term0_fast(float x) {
    float e = __expf(x);
    if (e < 0.0625f) {
        float gpoly = 1.0f + e * (-2.5f + e * (4.33333333f + e * (-6.41666667f)));
        return 0.75f * e * e * e * gpoly;
    }
    return term0_exact(x);
}
// exact t=1 focal term: alpha*(1-sigmoid(x))^2*softplus(-x)  (fg anchors only)
__device__ __forceinline__ float term1(float x) {
    float e   = __expf(-fabsf(x));
    float spn = fmaxf(-x, 0.0f) + __logf(1.0f + e);
    float rr  = __fdividef(1.0f, 1.0f + e);
    float p   = (x >= 0.0f) ? rr : e * rr;
    float q   = 1.0f - p;
    return 0.25f * q * q * spn;
}

// Kernel B: per-anchor matching (recompute IoU row), focal + smooth-L1,
// hierarchical reduction -> one double atomic set per block.
__global__ void __launch_bounds__(256) k_loss(
        const float*  __restrict__ logits,
        const float4* __restrict__ deltas,
        const float4* __restrict__ anchors,
        const float4* __restrict__ gt_boxes,
        const int*    __restrict__ gt_labels) {
    const int b = blockIdx.y;
    const int r = blockIdx.x * 256 + threadIdx.x;

    __shared__ float4 sG[64];
    __shared__ float2 sAM[64];   // (area_g, mp_or_-1)
    __shared__ int    sL[64];
    if (threadIdx.x < 64) {
        float4 gb = gt_boxes[b * G_GT + threadIdx.x];
        sG[threadIdx.x] = gb;
        float mp = __uint_as_float(d_mpg[b * G_GT + threadIdx.x]);
        // sentinel -1: iou (>=0) never equals it, folding away the mp>0 test
        sAM[threadIdx.x] = make_float2(box_area(gb), (mp > 0.0f) ? mp : -1.0f);
        sL[threadIdx.x]  = gt_labels[b * G_GT + threadIdx.x];
    }
    __syncthreads();

    float cls = 0.0f, box = 0.0f;
    int fg = 0;
    if (r < R_ANCH) {
        float4 a = anchors[r];
        float area_a = box_area(a);
        float best = -1.0f;
        int   bi = 0;
        int   lq = 0;
        #pragma unroll 8
        for (int gi = 0; gi < G_GT; gi++) {
            float2 am = sAM[gi];
            float iou = iou_core(a, area_a, sG[gi], am.x);
            if (iou > best) { best = iou; bi = gi; }   // first-index tie-break
            lq |= (iou == am.y);
        }
        fg = (best >= 0.5f) || lq;
        int valid = fg || (best < 0.4f);

        if (valid) {
            const float4* lp = (const float4*)(logits + ((size_t)b * R_ANCH + r) * C_CLS);
            #pragma unroll 4
            for (int c4 = 0; c4 < C_CLS / 4; c4++) {
                float4 v = lp[c4];
                cls += term0_fast(v.x) + term0_fast(v.y) +
                       term0_fast(v.z) + term0_fast(v.w);
            }
        }
        if (fg) {
            // swap matched class's t=0 term (same fast series) for its t=1 term
            float xm = logits[((size_t)b * R_ANCH + r) * C_CLS + sL[bi]];
            cls += term1(xm) - term0_fast(xm);

            float4 gb = sG[bi];
            float sw  = a.z - a.x,  sh  = a.w - a.y;
            float scx = a.x + 0.5f * sw, scy = a.y + 0.5f * sh;
            float tw  = gb.z - gb.x, th  = gb.w - gb.y;
            float tcx = gb.x + 0.5f * tw, tcy = gb.y + 0.5f * th;
            float gd0 = __fdividef(tcx - scx, sw);
            float gd1 = __fdividef(tcy - scy, sh);
            float gd2 = __logf(__fdividef(tw, sw));
            float gd3 = __logf(__fdividef(th, sh));
            float4 pd = deltas[(size_t)b * R_ANCH + r];
            float d0 = pd.x - gd0, d1 = pd.y - gd1, d2 = pd.z - gd2, d3 = pd.w - gd3;
            float a0 = fabsf(d0), a1 = fabsf(d1), a2 = fabsf(d2), a3 = fabsf(d3);
            // smooth L1, beta = 0.1
            box += (a0 < 0.1f) ? 5.0f * d0 * d0 : a0 - 0.05f;
            box += (a1 < 0.1f) ? 5.0f * d1 * d1 : a1 - 0.05f;
            box += (a2 < 0.1f) ? 5.0f * d2 * d2 : a2 - 0.05f;
            box += (a3 < 0.1f) ? 5.0f * d3 * d3 : a3 - 0.05f;
        }
    }

    // reduction: warp shuffle -> shared -> one atomic set per block
    const unsigned mask = 0xffffffffu;
    #pragma unroll
    for (int off = 16; off; off >>= 1) {
        cls += __shfl_xor_sync(mask, cls, off);
        box += __shfl_xor_sync(mask, box, off);
    }
    int wfg = __popc(__ballot_sync(mask, fg));

    __shared__ float rc[8], rb[8];
    __shared__ int   rf[8];
    int wid = threadIdx.x >> 5, lane = threadIdx.x & 31;
    if (lane == 0) { rc[wid] = cls; rb[wid] = box; rf[wid] = wfg; }
    __syncthreads();
    if (threadIdx.x == 0) {
        float tc = 0.f, tb = 0.f; int tf = 0;
        #pragma unroll
        for (int i = 0; i < 8; i++) { tc += rc[i]; tb += rb[i]; tf += rf[i]; }
        atomicAdd(&d_cls_sum, (double)tc);
        atomicAdd(&d_box_sum, (double)tb);
        atomicAdd(&d_fg_cnt, tf);
    }
}

// finalize AND reset scratch for the next replay (replay-idempotent)
__global__ void k_final(float* out) {
    int t = threadIdx.x;
    if (t == 0) {
        float norm = fmaxf(1.0f, (float)d_fg_cnt);
        out[0] = (float)(d_cls_sum / (double)norm);
        out[1] = (float)(d_box_sum / (double)norm);
        d_cls_sum = 0.0; d_box_sum = 0.0; d_fg_cnt = 0;
    }
    if (t < B_BATCH * G_GT) d_mpg[t] = 0u;
}

extern "C" void kernel_launch(void* const* d_in, const int* in_sizes, int n_in,
                              void* d_out, int out_size) {
    const float* logits  = nullptr;
    const float* deltas  = nullptr;
    const float* anchors = nullptr;
    const float* gtb     = nullptr;
    const int*   gtl     = nullptr;
    for (int i = 0; i < n_in; i++) {
        switch (in_sizes[i]) {
            case 38400000: logits  = (const float*)d_in[i]; break;  // [4,120000,80]
            case 1920000:  deltas  = (const float*)d_in[i]; break;  // [4,120000,4]
            case 480000:   anchors = (const float*)d_in[i]; break;  // [120000,4]
            case 1024:     gtb     = (const float*)d_in[i]; break;  // [4,64,4]
            case 256:      gtl     = (const int*)d_in[i];   break;  // [4,64]
            default: break;
        }
    }

    {
        dim3 grid(NTILES, B_BATCH);   // one 256-anchor tile per block
        k_maxpergt<<<grid, 256>>>((const float4*)anchors, (const float4*)gtb);
    }
    {
        dim3 grid((R_ANCH + 255) / 256, B_BATCH);
        k_loss<<<grid, 256>>>(logits, (const float4*)deltas,
                              (const float4*)anchors, (const float4*)gtb, gtl);
    }
    k_final<<<1, 256>>>((float*)d_out);
}